// round 7
// baseline (speedup 1.0000x reference)
#include <cuda_runtime.h>
#include <cuda_bf16.h>
#include <cstdint>

#define NN 25000
#define EE 400000
#define DD 256
#define FEAT 32
#define HOPS 4
#define SCAN_T 1024

// ---------------- device scratch (static, no allocation) ----------------
__device__ __align__(16) float g_h  [(size_t)NN * DD];
__device__ __align__(16) float g_h2 [(size_t)NN * DD];
__device__ __align__(16) float g_S  [(size_t)NN * DD];
__device__ __align__(16) float g_agg[(size_t)NN * DD];
__device__ __align__(16) float g_deg[NN];
__device__ __align__(16) float g_pool[DD];
__device__ int   g_cnt[NN];
__device__ int   g_rowptr[NN + 1];
__device__ int   g_pos[NN];
__device__ int   g_esrc[EE];
__device__ int   g_is64;

// read index idx from a buffer that is either int32 or int64
__device__ __forceinline__ int idx_at(const void* buf, int is64, size_t idx) {
    if (is64) return (int)((const long long*)buf)[idx];
    return ((const int*)buf)[idx];
}

// ---------------- dtype sniffer ----------------
__global__ void detect_kernel(const int* __restrict__ edges_w, int* __restrict__ is64) {
    __shared__ int nz;
    if (threadIdx.x == 0) nz = 0;
    __syncthreads();
    int any = 0;
    for (int t = threadIdx.x; t < 4096; t += blockDim.x)
        if (edges_w[2 * t + 1] != 0) any = 1;
    if (any) atomicAdd(&nz, 1);
    __syncthreads();
    if (threadIdx.x == 0) *is64 = (nz == 0) ? 1 : 0;
}

// ---------------- utility ----------------
__global__ void zero_i_kernel(int* __restrict__ p, int n) {
    int i = blockIdx.x * blockDim.x + threadIdx.x;
    if (i < n) p[i] = 0;
}
__global__ void zero_f_kernel(float* __restrict__ p, int n) {
    int i = blockIdx.x * blockDim.x + threadIdx.x;
    if (i < n) p[i] = 0.0f;
}

// ---------------- CSR build ----------------
__global__ void count_kernel(const void* __restrict__ edges, const int* __restrict__ is64p,
                             int* __restrict__ cnt) {
    int e = blockIdx.x * blockDim.x + threadIdx.x;
    if (e >= EE) return;
    int d = idx_at(edges, *is64p, (size_t)EE + e);
    if (d >= 0 && d < NN) atomicAdd(&cnt[d], 1);
}

__global__ void scan_kernel(const int* __restrict__ cnt, int* __restrict__ rowptr,
                            int* __restrict__ pos, float* __restrict__ deg) {
    __shared__ int part[SCAN_T];
    int t = threadIdx.x;
    const int CH = (NN + SCAN_T - 1) / SCAN_T;
    int base = t * CH;
    int s = 0;
#pragma unroll
    for (int i = 0; i < CH; ++i) {
        int idx = base + i;
        if (idx < NN) s += cnt[idx];
    }
    part[t] = s;
    __syncthreads();
    for (int off = 1; off < SCAN_T; off <<= 1) {
        int v = (t >= off) ? part[t - off] : 0;
        __syncthreads();
        part[t] += v;
        __syncthreads();
    }
    int prefix = (t == 0) ? 0 : part[t - 1];
#pragma unroll
    for (int i = 0; i < CH; ++i) {
        int idx = base + i;
        if (idx < NN) {
            rowptr[idx] = prefix;
            pos[idx] = prefix;
            int c = cnt[idx];
            deg[idx] = (float)c;
            prefix += c;
        }
    }
    if (t == SCAN_T - 1) rowptr[NN] = part[SCAN_T - 1];
}

__global__ void fill_kernel(const void* __restrict__ edges, const int* __restrict__ is64p,
                            int* __restrict__ pos, int* __restrict__ esrc) {
    int e = blockIdx.x * blockDim.x + threadIdx.x;
    if (e >= EE) return;
    int is64 = *is64p;
    int s = idx_at(edges, is64, (size_t)e);
    int d = idx_at(edges, is64, (size_t)EE + e);
    if (d < 0 || d >= NN) return;
    if (s < 0) s = 0; if (s >= NN) s = NN - 1;
    int slot = atomicAdd(&pos[d], 1);
    if (slot >= 0 && slot < EE) esrc[slot] = s;
}

// ---------------- initial node states ----------------
__global__ void init_kernel(const float* __restrict__ nodes,
                            const void* __restrict__ types, const int* __restrict__ is64p,
                            const float* __restrict__ type_emb,
                            const float* __restrict__ W_proj,
                            const float* __restrict__ b_proj,
                            float* __restrict__ h) {
    int v = blockIdx.x;
    int j = threadIdx.x;
    __shared__ float sn[FEAT];
    if (j < FEAT) sn[j] = nodes[(size_t)v * FEAT + j];
    __syncthreads();
    int t = idx_at(types, *is64p, (size_t)v);
    if (t < 0) t = 0; if (t > 9) t = 9;
    float acc = b_proj[j] + type_emb[(size_t)t * DD + j];
#pragma unroll
    for (int k = 0; k < FEAT; ++k)
        acc += sn[k] * W_proj[(size_t)k * DD + j];
    h[(size_t)v * DD + j] = acc;
}

// ---------------- per-dst gather: S[v] = sum over incoming edges of h[src] ----
__global__ __launch_bounds__(DD)
void agg_gather_kernel(const int* __restrict__ rowptr,
                       const int* __restrict__ esrc,
                       const float* __restrict__ h,
                       float* __restrict__ S) {
    int v = blockIdx.x;
    int j = threadIdx.x;
    int beg = rowptr[v];
    int end = rowptr[v + 1];
    float acc = 0.0f;
    int i = beg;
    for (; i + 4 <= end; i += 4) {
        int s0 = esrc[i + 0];
        int s1 = esrc[i + 1];
        int s2 = esrc[i + 2];
        int s3 = esrc[i + 3];
        float a0 = h[(size_t)s0 * DD + j];
        float a1 = h[(size_t)s1 * DD + j];
        float a2 = h[(size_t)s2 * DD + j];
        float a3 = h[(size_t)s3 * DD + j];
        acc += (a0 + a1) + (a2 + a3);
    }
    for (; i < end; ++i)
        acc += h[(size_t)esrc[i] * DD + j];
    S[(size_t)v * DD + j] = acc;
}

// ---------------- 3xTF32 mma.sync dual-operand GEMM ----------------
// out[r][c] = sum_k P[r][k]*W[k][c] + rowscale[r]*sum_k Q[r][k]*W[256+k][c]
//             + bias[c]*(bias_scaled ? rowscale[r] : 1),  optional relu
// Precision: x = hi + lo (both tf32); x*y ~= hi*hi + hi*lo + lo*hi  (~fp32 accuracy)
#define APAD 36
#define BPAD 136

__device__ __forceinline__ void mma_tf32(float* c, const uint32_t* a, const uint32_t* b) {
    asm volatile(
        "mma.sync.aligned.m16n8k8.row.col.f32.tf32.tf32.f32 "
        "{%0,%1,%2,%3}, {%4,%5,%6,%7}, {%8,%9}, {%0,%1,%2,%3};"
        : "+f"(c[0]), "+f"(c[1]), "+f"(c[2]), "+f"(c[3])
        : "r"(a[0]), "r"(a[1]), "r"(a[2]), "r"(a[3]), "r"(b[0]), "r"(b[1]));
}
__device__ __forceinline__ uint32_t f2tf(float x) {
    uint32_t r;
    asm("cvt.rna.tf32.f32 %0, %1;" : "=r"(r) : "f"(x));
    return r;
}
__device__ __forceinline__ void split_tf(float x, uint32_t& hi, uint32_t& lo) {
    hi = f2tf(x);
    lo = f2tf(x - __uint_as_float(hi));
}

__global__ __launch_bounds__(256)
void mma_gemm2_kernel(const float* __restrict__ P, const float* __restrict__ Q,
                      const float* __restrict__ W, const float* __restrict__ bias,
                      const float* __restrict__ rowscale,
                      int bias_scaled, int do_relu,
                      float* __restrict__ out) {
    __shared__ float As[128 * APAD];   // [m][k] tile 128x32 (full fp32)
    __shared__ float Bs[32 * BPAD];    // [k][n] tile 32x128 (full fp32)

    int tid = threadIdx.x;
    int wid = tid >> 5;
    int lane = tid & 31;
    int tq = lane >> 2;
    int tr = lane & 3;
    int warp_m = wid & 1;
    int warp_n = wid >> 1;
    int rowBase = blockIdx.y * 128;
    int colBase = blockIdx.x * 128;

    float acc[4][4][4];
#pragma unroll
    for (int mt = 0; mt < 4; ++mt)
#pragma unroll
        for (int nt = 0; nt < 4; ++nt)
#pragma unroll
            for (int q = 0; q < 4; ++q) acc[mt][nt][q] = 0.0f;

    int arow = tid >> 1;
    int ahalf = (tid & 1) * 16;
    int brow = tid >> 3;
    int bcol = (tid & 7) * 16;

#pragma unroll 1
    for (int p = 0; p < 2; ++p) {
        const float* X = p ? Q : P;
        bool scaled = (p == 1) && (rowscale != nullptr);
#pragma unroll 1
        for (int kt = 0; kt < 8; ++kt) {
            int k0 = kt * 32;
            __syncthreads();
            // load A tile [128][32]
            {
                int gr = rowBase + arow;
                float4 v[4];
                if (gr < NN) {
                    const float4* src = reinterpret_cast<const float4*>(
                        X + (size_t)gr * DD + k0 + ahalf);
#pragma unroll
                    for (int i = 0; i < 4; ++i) v[i] = src[i];
                    if (scaled) {
                        float sc = rowscale[gr];
#pragma unroll
                        for (int i = 0; i < 4; ++i) {
                            v[i].x *= sc; v[i].y *= sc; v[i].z *= sc; v[i].w *= sc;
                        }
                    }
                } else {
#pragma unroll
                    for (int i = 0; i < 4; ++i) v[i] = make_float4(0.f, 0.f, 0.f, 0.f);
                }
#pragma unroll
                for (int i = 0; i < 4; ++i)
                    *reinterpret_cast<float4*>(&As[arow * APAD + ahalf + i * 4]) = v[i];
            }
            // load B tile [32][128]
            {
                const float4* src = reinterpret_cast<const float4*>(
                    W + (size_t)(p * 256 + k0 + brow) * DD + colBase + bcol);
#pragma unroll
                for (int i = 0; i < 4; ++i)
                    *reinterpret_cast<float4*>(&Bs[brow * BPAD + bcol + i * 4]) = src[i];
            }
            __syncthreads();
            // compute: 4 k-steps of 8, 3-pass tf32
#pragma unroll
            for (int kk = 0; kk < 32; kk += 8) {
                uint32_t ah[4][4], al[4][4], bh[4][2], bl[4][2];
#pragma unroll
                for (int mt = 0; mt < 4; ++mt) {
                    int m0 = warp_m * 64 + mt * 16 + tq;
                    const float* ap = &As[m0 * APAD + kk + tr];
                    split_tf(ap[0],            ah[mt][0], al[mt][0]);
                    split_tf(ap[8 * APAD],     ah[mt][1], al[mt][1]);
                    split_tf(ap[4],            ah[mt][2], al[mt][2]);
                    split_tf(ap[8 * APAD + 4], ah[mt][3], al[mt][3]);
                }
#pragma unroll
                for (int nt = 0; nt < 4; ++nt) {
                    int n0 = warp_n * 32 + nt * 8 + tq;
                    const float* bp = &Bs[(kk + tr) * BPAD + n0];
                    split_tf(bp[0],        bh[nt][0], bl[nt][0]);
                    split_tf(bp[4 * BPAD], bh[nt][1], bl[nt][1]);
                }
#pragma unroll
                for (int mt = 0; mt < 4; ++mt)
#pragma unroll
                    for (int nt = 0; nt < 4; ++nt) {
                        mma_tf32(acc[mt][nt], ah[mt], bl[nt]);
                        mma_tf32(acc[mt][nt], al[mt], bh[nt]);
                        mma_tf32(acc[mt][nt], ah[mt], bh[nt]);
                    }
            }
        }
    }

    // epilogue
#pragma unroll
    for (int mt = 0; mt < 4; ++mt) {
        int r0 = rowBase + warp_m * 64 + mt * 16 + tq;
        int r1 = r0 + 8;
        float bs0 = 1.0f, bs1 = 1.0f;
        if (bias_scaled) {
            if (r0 < NN) bs0 = rowscale[r0];
            if (r1 < NN) bs1 = rowscale[r1];
        }
#pragma unroll
        for (int nt = 0; nt < 4; ++nt) {
            int c = colBase + warp_n * 32 + nt * 8 + tr * 2;
            float b0 = bias[c], b1 = bias[c + 1];
            if (r0 < NN) {
                float2 v;
                v.x = acc[mt][nt][0] + b0 * bs0;
                v.y = acc[mt][nt][1] + b1 * bs0;
                if (do_relu) { v.x = fmaxf(v.x, 0.f); v.y = fmaxf(v.y, 0.f); }
                *reinterpret_cast<float2*>(out + (size_t)r0 * DD + c) = v;
            }
            if (r1 < NN) {
                float2 v;
                v.x = acc[mt][nt][2] + b0 * bs1;
                v.y = acc[mt][nt][3] + b1 * bs1;
                if (do_relu) { v.x = fmaxf(v.x, 0.f); v.y = fmaxf(v.y, 0.f); }
                *reinterpret_cast<float2*>(out + (size_t)r1 * DD + c) = v;
            }
        }
    }
}

// ---------------- max pool over nodes ----------------
__global__ void pool_kernel(const float* __restrict__ h, float* __restrict__ pool) {
    int j = threadIdx.x;
    int r0 = blockIdx.x * 256;
    int r1 = min(r0 + 256, NN);
    float m = 0.0f;
    for (int r = r0; r < r1; ++r)
        m = fmaxf(m, h[(size_t)r * DD + j]);
    atomicMax(reinterpret_cast<int*>(&pool[j]), __float_as_int(m));
}

// ---------------- final projection ----------------
__global__ void out_kernel(const float* __restrict__ pool,
                           const float* __restrict__ W_out,
                           const float* __restrict__ b_out,
                           float* __restrict__ out) {
    __shared__ float sp[DD];
    int j = threadIdx.x;
    sp[j] = pool[j];
    __syncthreads();
    float acc = b_out[j];
#pragma unroll 8
    for (int k = 0; k < DD; ++k)
        acc += sp[k] * W_out[(size_t)k * DD + j];
    out[j] = acc;
}

// ---------------- launch ----------------
extern "C" void kernel_launch(void* const* d_in, const int* in_sizes, int n_in,
                              void* d_out, int out_size) {
    const float* nodes      = (const float*)d_in[0];
    const void*  edges      = d_in[1];
    const void*  node_types = d_in[2];
    const float* type_emb   = (const float*)d_in[3];
    const float* W_proj     = (const float*)d_in[4];
    const float* b_proj     = (const float*)d_in[5];
    const float* W_msg      = (const float*)d_in[6];   // [4][512][256]
    const float* b_msg      = (const float*)d_in[7];
    const float* W_upd      = (const float*)d_in[8];   // [4][512][256]
    const float* b_upd      = (const float*)d_in[9];
    const float* W_out      = (const float*)d_in[10];
    const float* b_out      = (const float*)d_in[11];
    float* out = (float*)d_out;

    float *h_p, *h2_p, *S_p, *agg_p, *deg_p, *pool_p;
    int *cnt_p, *rowptr_p, *pos_p, *esrc_p, *is64_p;
    cudaGetSymbolAddress((void**)&h_p,      g_h);
    cudaGetSymbolAddress((void**)&h2_p,     g_h2);
    cudaGetSymbolAddress((void**)&S_p,      g_S);
    cudaGetSymbolAddress((void**)&agg_p,    g_agg);
    cudaGetSymbolAddress((void**)&deg_p,    g_deg);
    cudaGetSymbolAddress((void**)&pool_p,   g_pool);
    cudaGetSymbolAddress((void**)&cnt_p,    g_cnt);
    cudaGetSymbolAddress((void**)&rowptr_p, g_rowptr);
    cudaGetSymbolAddress((void**)&pos_p,    g_pos);
    cudaGetSymbolAddress((void**)&esrc_p,   g_esrc);
    cudaGetSymbolAddress((void**)&is64_p,   g_is64);

    // sniff index dtype
    detect_kernel<<<1, 256>>>((const int*)edges, is64_p);

    // CSR build
    zero_i_kernel<<<(NN + 255) / 256, 256>>>(cnt_p, NN);
    count_kernel<<<(EE + 255) / 256, 256>>>(edges, is64_p, cnt_p);
    scan_kernel<<<1, SCAN_T>>>(cnt_p, rowptr_p, pos_p, deg_p);
    fill_kernel<<<(EE + 255) / 256, 256>>>(edges, is64_p, pos_p, esrc_p);

    // initial states
    init_kernel<<<NN, DD>>>(nodes, node_types, is64_p, type_emb, W_proj, b_proj, h_p);

    float* h_cur = h_p;
    float* h_nxt = h2_p;
    dim3 ggrid(2, (NN + 127) / 128);

    for (int i = 0; i < HOPS; ++i) {
        agg_gather_kernel<<<NN, DD>>>(rowptr_p, esrc_p, h_cur, S_p);
        // agg = S @ Wm_top + deg .* (h @ Wm_bot) + deg .* b_msg
        mma_gemm2_kernel<<<ggrid, 256>>>(S_p, h_cur,
                                         W_msg + (size_t)i * 2 * DD * DD,
                                         b_msg + (size_t)i * DD,
                                         deg_p, 1, 0, agg_p);
        // h_next = relu(h @ Wu_top + agg @ Wu_bot + b_upd)
        mma_gemm2_kernel<<<ggrid, 256>>>(h_cur, agg_p,
                                         W_upd + (size_t)i * 2 * DD * DD,
                                         b_upd + (size_t)i * DD,
                                         nullptr, 0, 1, h_nxt);
        float* t = h_cur; h_cur = h_nxt; h_nxt = t;
    }

    // pool + output
    zero_f_kernel<<<1, DD>>>(pool_p, DD);
    pool_kernel<<<(NN + 255) / 256, DD>>>(h_cur, pool_p);
    out_kernel<<<1, DD>>>(pool_p, W_out, b_out, out);
}